// round 13
// baseline (speedup 1.0000x reference)
#include <cuda_runtime.h>
#include <cuda_fp16.h>
#include <cstdint>

// GridSample1d: N=64, C=64, L_in=4096, L_out=8192, fp32 in/out,
// align_corners=True, padding=border.
//
// R13: R9 pipeline (CG=4 fp16-interleaved swizzled gather, 256 thr,
// double-buffered 2x32KB input staging, VEC=4) + TMA bulk output stores:
// results go to 2x16KB SMEM out buffers via conflict-free STS.128, then
// cp.async.bulk.global.shared::cta (4x4KB per iter) moves them to GMEM on
// the TMA engine -> removes ~12us of STG issue from the LSU.
// 96KB smem -> 2 blocks/SM, 296 persistent blocks.

#define N_B     64
#define C_TOT   64
#define L_IN    4096
#define L_OUT   8192
#define CG      4
#define TILES   1024
#define THREADS 256
#define BLOCKS  296                 // 2 * 148 SMs
#define BUF_B   (L_IN * 8)          // 32 KB input buffer (uint2 per position)
#define OBUF_B  16384               // 16 KB out buffer (4 ch x 1024 l_out x 4B)
#define VEC     4
#define GITERS  8

__device__ __forceinline__ uint32_t swz(uint32_t o) {
    return o ^ ((o >> 3) & 0x70);
}
__device__ __forceinline__ uint32_t packh2(float a, float b) {
    __half2 h = __floats2half2_rn(a, b);
    return *reinterpret_cast<uint32_t*>(&h);
}
__device__ __forceinline__ uint32_t s2u(const void* p) {
    return (uint32_t)__cvta_generic_to_shared(p);
}

__device__ __forceinline__ void bulk_copy_g_s(void* gdst, uint32_t ssrc, uint32_t bytes) {
    asm volatile("cp.async.bulk.global.shared::cta.bulk_group [%0], [%1], %2;"
                 :: "l"(gdst), "r"(ssrc), "r"(bytes) : "memory");
}
__device__ __forceinline__ void bulk_commit() {
    asm volatile("cp.async.bulk.commit_group;" ::: "memory");
}
__device__ __forceinline__ void bulk_wait_read_1() {
    asm volatile("cp.async.bulk.wait_group.read 1;" ::: "memory");
}
__device__ __forceinline__ void bulk_wait_all() {
    asm volatile("cp.async.bulk.wait_group 0;" ::: "memory");
}
__device__ __forceinline__ void fence_async_shared() {
    asm volatile("fence.proxy.async.shared::cta;" ::: "memory");
}

__device__ __forceinline__ void ldg_chunk(const float* ibase, int i0, float4 a[CG]) {
    #pragma unroll
    for (int c = 0; c < CG; ++c)
        a[c] = __ldcs(reinterpret_cast<const float4*>(ibase + (size_t)c * L_IN + i0));
}
__device__ __forceinline__ void sts_chunk(char* buf, int i0, const float4 a[CG]) {
    #pragma unroll
    for (int k = 0; k < 4; ++k) {
        uint2 v;
        v.x = packh2(((const float*)&a[0])[k], ((const float*)&a[1])[k]);
        v.y = packh2(((const float*)&a[2])[k], ((const float*)&a[3])[k]);
        *reinterpret_cast<uint2*>(buf + swz((uint32_t)(i0 + k) * 8u)) = v;
    }
}

// gather iteration it: compute r, STS into out buffer, TMA-copy to gmem.
__device__ __forceinline__ void gather_iter(int it, int tid, const char* cur,
                                            const float* grow, float* obase,
                                            char* obuf, float scale) {
    const int l0 = it * (THREADS * VEC) + tid * VEC;
    const float4 g = __ldg(reinterpret_cast<const float4*>(grow + l0));
    const float xs[VEC] = {g.x, g.y, g.z, g.w};
    float r[CG][VEC];

    #pragma unroll
    for (int j = 0; j < VEC; ++j) {
        float x = (xs[j] + 1.0f) * scale;               // align_corners
        x = fminf(fmaxf(x, 0.0f), (float)(L_IN - 1));   // border clamp
        float xf = floorf(x);
        int   i0 = (int)xf;
        float w1 = x - xf;
        float w0 = 1.0f - w1;
        int   i1 = min(i0 + 1, L_IN - 1);

        const uint2 p0 = *reinterpret_cast<const uint2*>(cur + swz((uint32_t)i0 * 8u));
        const uint2 p1 = *reinterpret_cast<const uint2*>(cur + swz((uint32_t)i1 * 8u));

        float2 v0a = __half22float2(*reinterpret_cast<const __half2*>(&p0.x));
        float2 v0b = __half22float2(*reinterpret_cast<const __half2*>(&p0.y));
        float2 v1a = __half22float2(*reinterpret_cast<const __half2*>(&p1.x));
        float2 v1b = __half22float2(*reinterpret_cast<const __half2*>(&p1.y));

        r[0][j] = w0 * v0a.x + w1 * v1a.x;
        r[1][j] = w0 * v0a.y + w1 * v1a.y;
        r[2][j] = w0 * v0b.x + w1 * v1b.x;
        r[3][j] = w0 * v0b.y + w1 * v1b.y;
    }

    // recycle this out buffer: copy issued 2 iterations ago must have been read
    if (tid == 0) bulk_wait_read_1();
    __syncthreads();

    #pragma unroll
    for (int c = 0; c < CG; ++c) {
        float4 o = make_float4(r[c][0], r[c][1], r[c][2], r[c][3]);
        *reinterpret_cast<float4*>(obuf + c * 4096 + tid * 16) = o;
    }
    __syncthreads();

    if (tid == 0) {
        fence_async_shared();
        const uint32_t src = s2u(obuf);
        #pragma unroll
        for (int c = 0; c < CG; ++c)
            bulk_copy_g_s(obase + (size_t)c * L_OUT + it * (THREADS * VEC),
                          src + c * 4096, 4096);
        bulk_commit();
    }
}

__global__ __launch_bounds__(THREADS)
void gs1d_kernel(const float* __restrict__ inp,
                 const float* __restrict__ grid,
                 float* __restrict__ out)
{
    extern __shared__ char s_raw[];   // [0,32K) ibuf0 [32K,64K) ibuf1 [64K,96K) obufs

    const int tid = threadIdx.x;
    const int b   = blockIdx.x;
    const float scale = 0.5f * (float)(L_IN - 1);
    const int iq0 = tid * 4;          // staging chunks at iq0 + q*1024

    char* obufs = s_raw + 2 * BUF_B;

    // ---- prologue: stage first tile into ibuf0 ----
    {
        const int t = b;
        const int n = t >> 4, c0 = (t & 15) * CG;
        const float* ibase = inp + ((size_t)n * C_TOT + c0) * L_IN;
        float4 a[CG];
        #pragma unroll
        for (int q = 0; q < 4; ++q) {
            ldg_chunk(ibase, iq0 + q * 1024, a);
            sts_chunk(s_raw, iq0 + q * 1024, a);
        }
    }
    __syncthreads();

    int k = 0;
    for (int t = b; t < TILES; t += BLOCKS, ++k) {
        char* cur = s_raw + (k & 1) * BUF_B;
        char* nxt = s_raw + ((k + 1) & 1) * BUF_B;

        const int n = t >> 4, c0 = (t & 15) * CG;
        const float* grow  = grid + (size_t)n * L_OUT;
        float*       obase = out  + ((size_t)n * C_TOT + c0) * L_OUT;

        const int  tn       = t + BLOCKS;
        const bool has_next = (tn < TILES);
        const float* nbase  = inp;
        if (has_next) {
            const int nn = tn >> 4, nc0 = (tn & 15) * CG;
            nbase = inp + ((size_t)nn * C_TOT + nc0) * L_IN;
        }

        float4 a[CG];
        if (has_next) ldg_chunk(nbase, iq0, a);
        gather_iter(0, tid, cur, grow, obase, obufs + 0 * OBUF_B, scale);
        if (has_next) { sts_chunk(nxt, iq0, a); ldg_chunk(nbase, iq0 + 1024, a); }
        gather_iter(1, tid, cur, grow, obase, obufs + 1 * OBUF_B, scale);
        if (has_next) { sts_chunk(nxt, iq0 + 1024, a); ldg_chunk(nbase, iq0 + 2048, a); }
        gather_iter(2, tid, cur, grow, obase, obufs + 0 * OBUF_B, scale);
        if (has_next) { sts_chunk(nxt, iq0 + 2048, a); ldg_chunk(nbase, iq0 + 3072, a); }
        gather_iter(3, tid, cur, grow, obase, obufs + 1 * OBUF_B, scale);
        if (has_next) sts_chunk(nxt, iq0 + 3072, a);
        gather_iter(4, tid, cur, grow, obase, obufs + 0 * OBUF_B, scale);
        gather_iter(5, tid, cur, grow, obase, obufs + 1 * OBUF_B, scale);
        gather_iter(6, tid, cur, grow, obase, obufs + 0 * OBUF_B, scale);
        gather_iter(7, tid, cur, grow, obase, obufs + 1 * OBUF_B, scale);
        __syncthreads();   // nxt fully staged; cur free for reuse
    }

    // ensure all TMA stores fully complete before block exit
    if (tid == 0) bulk_wait_all();
}

extern "C" void kernel_launch(void* const* d_in, const int* in_sizes, int n_in,
                              void* d_out, int out_size)
{
    const float* inp  = (const float*)d_in[0];  // [64, 64, 4096]
    const float* grid = (const float*)d_in[1];  // [64, 8192]
    float*       out  = (float*)d_out;          // [64, 64, 8192]

    const int smem_bytes = 2 * BUF_B + 2 * OBUF_B;   // 96 KB
    cudaFuncSetAttribute(gs1d_kernel,
                         cudaFuncAttributeMaxDynamicSharedMemorySize,
                         smem_bytes);

    gs1d_kernel<<<BLOCKS, THREADS, smem_bytes>>>(inp, grid, out);
}

// round 14
// speedup vs baseline: 1.3489x; 1.3489x over previous
#include <cuda_runtime.h>
#include <cuda_fp16.h>
#include <cstdint>

// GridSample1d: N=64, C=64, L_in=4096, L_out=8192, fp32 in/out,
// align_corners=True, padding=border.
//
// R14: R9 base (CG=4 fp16-interleaved swizzled gather, 256 thr, 444 blocks
// 3/SM, 2x32KB double buffer, VEC=4/STG.128) + minimal tail fix:
//   item 0: tile b          (8 gather iters, stages item1 tile)
//   item 1: tile b+444      (8 gather iters, stages item2 tile if any)
//   item 2 (blocks 0..271): tile 888+b/2, l_out half b&1 (4 iters, no stage)
// Round 2 wall time ~halves vs R9's 31%-occupied 3rd round.

#define N_B     64
#define C_TOT   64
#define L_IN    4096
#define L_OUT   8192
#define CG      4
#define TILES   1024
#define THREADS 256
#define BLOCKS  444
#define BUF_B   (L_IN * 8)          // 32 KB per buffer (uint2 per position)
#define VEC     4

__device__ __forceinline__ uint32_t swz(uint32_t o) {
    return o ^ ((o >> 3) & 0x70);
}
__device__ __forceinline__ uint32_t packh2(float a, float b) {
    __half2 h = __floats2half2_rn(a, b);
    return *reinterpret_cast<uint32_t*>(&h);
}

__device__ __forceinline__ const float* tile_base(const float* inp, int t) {
    const int n = t >> 4, c0 = (t & 15) * CG;
    return inp + ((size_t)n * C_TOT + c0) * L_IN;
}

__device__ __forceinline__ void ldg_chunk(const float* ibase, int i0, float4 a[CG]) {
    #pragma unroll
    for (int c = 0; c < CG; ++c)
        a[c] = __ldcs(reinterpret_cast<const float4*>(ibase + (size_t)c * L_IN + i0));
}
__device__ __forceinline__ void sts_chunk(char* buf, int i0, const float4 a[CG]) {
    #pragma unroll
    for (int k = 0; k < 4; ++k) {
        uint2 v;
        v.x = packh2(((const float*)&a[0])[k], ((const float*)&a[1])[k]);
        v.y = packh2(((const float*)&a[2])[k], ((const float*)&a[3])[k]);
        *reinterpret_cast<uint2*>(buf + swz((uint32_t)(i0 + k) * 8u)) = v;
    }
}

__device__ __forceinline__ void gather_iter_at(int l0, const char* cur,
                                               const float* grow, float* obase,
                                               float scale) {
    const float4 g = __ldg(reinterpret_cast<const float4*>(grow + l0));
    const float xs[VEC] = {g.x, g.y, g.z, g.w};
    float r[CG][VEC];

    #pragma unroll
    for (int j = 0; j < VEC; ++j) {
        float x = (xs[j] + 1.0f) * scale;               // align_corners
        x = fminf(fmaxf(x, 0.0f), (float)(L_IN - 1));   // border clamp
        float xf = floorf(x);
        int   i0 = (int)xf;
        float w1 = x - xf;
        float w0 = 1.0f - w1;
        int   i1 = min(i0 + 1, L_IN - 1);

        const uint2 p0 = *reinterpret_cast<const uint2*>(cur + swz((uint32_t)i0 * 8u));
        const uint2 p1 = *reinterpret_cast<const uint2*>(cur + swz((uint32_t)i1 * 8u));

        float2 v0a = __half22float2(*reinterpret_cast<const __half2*>(&p0.x));
        float2 v0b = __half22float2(*reinterpret_cast<const __half2*>(&p0.y));
        float2 v1a = __half22float2(*reinterpret_cast<const __half2*>(&p1.x));
        float2 v1b = __half22float2(*reinterpret_cast<const __half2*>(&p1.y));

        r[0][j] = w0 * v0a.x + w1 * v1a.x;
        r[1][j] = w0 * v0a.y + w1 * v1a.y;
        r[2][j] = w0 * v0b.x + w1 * v1b.x;
        r[3][j] = w0 * v0b.y + w1 * v1b.y;
    }

    #pragma unroll
    for (int c = 0; c < CG; ++c) {
        float4 o = make_float4(r[c][0], r[c][1], r[c][2], r[c][3]);
        __stcs(reinterpret_cast<float4*>(obase + (size_t)c * L_OUT + l0), o);
    }
}

__global__ __launch_bounds__(THREADS)
void gs1d_kernel(const float* __restrict__ inp,
                 const float* __restrict__ grid,
                 float* __restrict__ out)
{
    extern __shared__ char s_raw[];   // 2 x 32 KB, swizzled fp16-interleaved

    const int tid = threadIdx.x;
    const int b   = blockIdx.x;
    const float scale = 0.5f * (float)(L_IN - 1);
    const int iq0 = tid * 4;          // staging chunks at iq0 + q*1024

    const bool hasTail = (b < 272);
    const int  tTail   = 888 + (b >> 1);
    const int  lTail   = (b & 1) * 4096;   // which l_out half
    const int  nItems  = hasTail ? 3 : 2;

    // ---- prologue: stage tile b into buf 0 ----
    {
        const float* ibase = tile_base(inp, b);
        float4 a[CG];
        #pragma unroll
        for (int q = 0; q < 4; ++q) {
            ldg_chunk(ibase, iq0 + q * 1024, a);
            sts_chunk(s_raw, iq0 + q * 1024, a);
        }
    }
    __syncthreads();

    for (int k = 0; k < nItems; ++k) {
        char* cur = s_raw + (k & 1) * BUF_B;
        char* nxt = s_raw + ((k + 1) & 1) * BUF_B;

        // current item
        const int t  = (k < 2) ? (b + k * 444) : tTail;
        const int lo = (k < 2) ? 0 : lTail;
        const int n  = t >> 4, c0 = (t & 15) * CG;
        const float* grow  = grid + (size_t)n * L_OUT;
        float*       obase = out  + ((size_t)n * C_TOT + c0) * L_OUT;

        if (k < 2) {
            // full tile: 8 gather iters, stage next item's tile interleaved
            const bool has_next = (k + 1 < nItems);
            const float* nbase  = inp;
            if (has_next) {
                const int tn = (k == 0) ? (b + 444) : tTail;
                nbase = tile_base(inp, tn);
            }

            float4 a[CG];
            if (has_next) ldg_chunk(nbase, iq0, a);
            gather_iter_at(0 * 1024 + tid * VEC, cur, grow, obase, scale);
            if (has_next) { sts_chunk(nxt, iq0, a); ldg_chunk(nbase, iq0 + 1024, a); }
            gather_iter_at(1 * 1024 + tid * VEC, cur, grow, obase, scale);
            if (has_next) { sts_chunk(nxt, iq0 + 1024, a); ldg_chunk(nbase, iq0 + 2048, a); }
            gather_iter_at(2 * 1024 + tid * VEC, cur, grow, obase, scale);
            if (has_next) { sts_chunk(nxt, iq0 + 2048, a); ldg_chunk(nbase, iq0 + 3072, a); }
            gather_iter_at(3 * 1024 + tid * VEC, cur, grow, obase, scale);
            if (has_next) sts_chunk(nxt, iq0 + 3072, a);
            gather_iter_at(4 * 1024 + tid * VEC, cur, grow, obase, scale);
            gather_iter_at(5 * 1024 + tid * VEC, cur, grow, obase, scale);
            gather_iter_at(6 * 1024 + tid * VEC, cur, grow, obase, scale);
            gather_iter_at(7 * 1024 + tid * VEC, cur, grow, obase, scale);
            __syncthreads();
        } else {
            // tail half-tile: 4 gather iters, nothing to stage
            #pragma unroll
            for (int it = 0; it < 4; ++it)
                gather_iter_at(lo + it * 1024 + tid * VEC, cur, grow, obase, scale);
        }
    }
}

extern "C" void kernel_launch(void* const* d_in, const int* in_sizes, int n_in,
                              void* d_out, int out_size)
{
    const float* inp  = (const float*)d_in[0];  // [64, 64, 4096]
    const float* grid = (const float*)d_in[1];  // [64, 8192]
    float*       out  = (float*)d_out;          // [64, 64, 8192]

    const int smem_bytes = 2 * BUF_B;           // 64 KB
    cudaFuncSetAttribute(gs1d_kernel,
                         cudaFuncAttributeMaxDynamicSharedMemorySize,
                         smem_bytes);

    gs1d_kernel<<<BLOCKS, THREADS, smem_bytes>>>(inp, grid, out);
}